// round 10
// baseline (speedup 1.0000x reference)
#include <cuda_runtime.h>
#include <cuda_bf16.h>
#include <cuda_fp16.h>
#include <cstddef>
#include <cstdint>

// ---------------------------------------------------------------------------
// 2-layer GCN. Per layer:  s = dinv * (A @ W);  agg[d] = s[d] + sum s[u];
//                          h = dinv * agg + b
// GEMMs: mma.sync bf16 hi/lo split (3 MMAs, ~fp32 precision), K in 64-chunks.
// Messages/agg1 fp16 (fp32 accum). CSR built once; rowptr via single-kernel
// decoupled-lookback scan.
// ---------------------------------------------------------------------------

#define NMAX 100000
#define EMAX 1700000
#define HID 128
#define ODIM 64
#define SCAN_BLK 512
#define MAXSB 256      // max scan blocks (196 used)
#define KP 72          // padded K-chunk stride (conflict-free frag LDS)

__device__ float  g_dinv[NMAX];
__device__ __align__(16) __half g_s1[(size_t)NMAX * HID];     // fp16 messages, layer 1
__device__ __align__(16) __half g_agg1h[(size_t)NMAX * HID];  // fp16 aggregate
__device__ __align__(16) __half g_s2[(size_t)NMAX * ODIM];    // fp16 messages, layer 2
__device__ int    g_is64;

__device__ int g_cnt[NMAX];
__device__ int g_rowptr[NMAX + 1];
__device__ int g_cursor[NMAX];
__device__ int g_csr[EMAX];

__device__ volatile int g_flag[MAXSB];   // 0=invalid 1=aggregate 2=inclusive
__device__ int g_aggval[MAXSB];
__device__ int g_incval[MAXSB];

__device__ __align__(16) __nv_bfloat16 g_w1t_hi[HID * HID], g_w1t_lo[HID * HID];   // [n][k]
__device__ __align__(16) __nv_bfloat16 g_w2t_hi[ODIM * HID], g_w2t_lo[ODIM * HID]; // [n][k]

// ---- fused pre-pass: dtype detect + cnt/flag zero + W conversion -------------
__global__ void k_pre(const int* __restrict__ ew,
                      const float* __restrict__ W1, const float* __restrict__ W2, int n)
{
    int i = blockIdx.x * blockDim.x + threadIdx.x;

    if (blockIdx.x == 0) {
        __shared__ int any;
        if (threadIdx.x == 0) any = 0;
        __syncthreads();
        for (int j = threadIdx.x; j < 2048; j += blockDim.x)
            if (ew[2 * j + 1] != 0) any = 1;
        __syncthreads();
        if (threadIdx.x == 0) g_is64 = (any == 0) ? 1 : 0;
    }

    if (i < n) g_cnt[i] = 0;
    if (i < MAXSB) g_flag[i] = 0;

    if (i < HID * HID) {
        int nn = i >> 7, k = i & 127;
        float v = W1[k * HID + nn];
        __nv_bfloat16 h = __float2bfloat16(v);
        g_w1t_hi[i] = h;
        g_w1t_lo[i] = __float2bfloat16(v - __bfloat162float(h));
    }
    if (i < ODIM * HID) {
        int nn = i >> 7, k = i & 127;
        float v = W2[k * ODIM + nn];
        __nv_bfloat16 h = __float2bfloat16(v);
        g_w2t_hi[i] = h;
        g_w2t_lo[i] = __float2bfloat16(v - __bfloat162float(h));
    }
}

__device__ __forceinline__ int edge_at(const int* __restrict__ w, int i, int is64) {
    return is64 ? w[2 * (size_t)i] : w[i];
}

// ---- CSR build ----------------------------------------------------------------
__global__ void k_count(const int* __restrict__ w, int E) {
    int is64 = g_is64;
    const int* dst = w + (size_t)E * (1 + is64);
    int i = blockIdx.x * blockDim.x + threadIdx.x;
    if (i < E) atomicAdd(&g_cnt[edge_at(dst, i, is64)], 1);
}

// single-pass decoupled-lookback exclusive scan of g_cnt -> rowptr/cursor/dinv
__global__ void k_scan(int n, int E) {
    __shared__ int sh[SCAN_BLK];
    __shared__ int s_prefix;
    const int b = blockIdx.x;
    const int tid = threadIdx.x;
    const int i = b * SCAN_BLK + tid;

    int v = (i < n) ? g_cnt[i] : 0;
    sh[tid] = v;
    __syncthreads();
    for (int off = 1; off < SCAN_BLK; off <<= 1) {
        int t = (tid >= off) ? sh[tid - off] : 0;
        __syncthreads();
        sh[tid] += t;
        __syncthreads();
    }
    const int total = sh[SCAN_BLK - 1];

    if (tid == 0) {
        if (b == 0) {
            s_prefix = 0;
            g_incval[0] = total;
            __threadfence();
            g_flag[0] = 2;
        } else {
            g_aggval[b] = total;
            __threadfence();
            g_flag[b] = 1;
            // lookback
            int pref = 0;
            int j = b - 1;
            while (true) {
                int f;
                do { f = g_flag[j]; } while (f == 0);
                __threadfence();
                if (f == 2) { pref += g_incval[j]; break; }
                pref += g_aggval[j];
                j--;
            }
            s_prefix = pref;
            g_incval[b] = pref + total;
            __threadfence();
            g_flag[b] = 2;
        }
    }
    __syncthreads();
    const int pref = s_prefix;

    if (i < n) {
        int rp = pref + sh[tid] - v;   // exclusive
        g_rowptr[i] = rp;
        g_cursor[i] = rp;
        g_dinv[i]   = rsqrtf((float)v + 1.0f);
        if (i == n - 1) g_rowptr[n] = E;
    }
}

__global__ void k_fill(const int* __restrict__ w, int E) {
    int is64 = g_is64;
    const int* src = w;
    const int* dst = w + (size_t)E * (1 + is64);
    int i = blockIdx.x * blockDim.x + threadIdx.x;
    if (i < E) {
        int u = edge_at(src, i, is64);
        int v = edge_at(dst, i, is64);
        int pos = atomicAdd(&g_cursor[v], 1);
        g_csr[pos] = u;
    }
}

// ---- tensor-core GEMM -----------------------------------------------------------
__device__ __forceinline__ void mma16816(float c[4], const uint32_t a[4], const uint32_t b[2]) {
    asm volatile(
        "mma.sync.aligned.m16n8k16.row.col.f32.bf16.bf16.f32 "
        "{%0,%1,%2,%3}, {%4,%5,%6,%7}, {%8,%9}, {%0,%1,%2,%3};\n"
        : "+f"(c[0]), "+f"(c[1]), "+f"(c[2]), "+f"(c[3])
        : "r"(a[0]), "r"(a[1]), "r"(a[2]), "r"(a[3]), "r"(b[0]), "r"(b[1]));
}

__device__ __forceinline__ uint32_t pack_bf2(__nv_bfloat16 a, __nv_bfloat16 b) {
    return (uint32_t)__bfloat16_as_ushort(a) | ((uint32_t)__bfloat16_as_ushort(b) << 16);
}

// Block: 128 rows x NOUT cols, 256 threads (8 warps, each m16 x NOUT).
// K processed in two 64-chunks.
// LAYER==1: A = x (fp32).  LAYER==2: A = g_agg1h (fp16), dinv*v + b1 fused on load.
// Epilogue: s_out(fp16) = dinv[row] * acc.
template <int NOUT, int LAYER>
__global__ void __launch_bounds__(256) k_tgemm(
    const float* __restrict__ A_in, const float* __restrict__ bias, int n)
{
    constexpr int NT = NOUT / 8;
    extern __shared__ __nv_bfloat16 sm[];
    __nv_bfloat16* Ahi = sm;                    // [128][KP]
    __nv_bfloat16* Alo = Ahi + 128 * KP;
    __nv_bfloat16* Bhi = Alo + 128 * KP;        // [NOUT][KP]
    __nv_bfloat16* Blo = Bhi + NOUT * KP;

    __half* s_out = (LAYER == 1) ? g_s1 : g_s2;
    const __nv_bfloat16* Wh = (LAYER == 1) ? g_w1t_hi : g_w2t_hi;
    const __nv_bfloat16* Wl = (LAYER == 1) ? g_w1t_lo : g_w2t_lo;

    const int tid  = threadIdx.x;
    const int row0 = blockIdx.x * 128;
    const int w = tid >> 5, lane = tid & 31;
    const int g = lane >> 2, tq = lane & 3;
    const int mrow = w * 16;

    float acc[NT][4];
#pragma unroll
    for (int nt = 0; nt < NT; nt++)
#pragma unroll
        for (int j = 0; j < 4; j++) acc[nt][j] = 0.0f;

#pragma unroll
    for (int kk = 0; kk < 128; kk += 64) {
        if (kk) __syncthreads();

        for (int base = tid * 4; base < 128 * 64; base += 256 * 4) {
            int r = base >> 6, k = base & 63;
            int row = row0 + r;
            float4 v = make_float4(0.f, 0.f, 0.f, 0.f);
            if (row < n) {
                if (LAYER == 1) {
                    v = *reinterpret_cast<const float4*>(&A_in[(size_t)row * 128 + kk + k]);
                } else {
                    uint2 hv = *reinterpret_cast<const uint2*>(&g_agg1h[(size_t)row * 128 + kk + k]);
                    float2 p0 = __half22float2(*reinterpret_cast<__half2*>(&hv.x));
                    float2 p1 = __half22float2(*reinterpret_cast<__half2*>(&hv.y));
                    float d = g_dinv[row];
                    float4 bb = *reinterpret_cast<const float4*>(&bias[kk + k]);
                    v.x = fmaf(d, p0.x, bb.x); v.y = fmaf(d, p0.y, bb.y);
                    v.z = fmaf(d, p1.x, bb.z); v.w = fmaf(d, p1.y, bb.w);
                }
            }
            __nv_bfloat16 h0 = __float2bfloat16(v.x), h1 = __float2bfloat16(v.y);
            __nv_bfloat16 h2 = __float2bfloat16(v.z), h3 = __float2bfloat16(v.w);
            __nv_bfloat16 l0 = __float2bfloat16(v.x - __bfloat162float(h0));
            __nv_bfloat16 l1 = __float2bfloat16(v.y - __bfloat162float(h1));
            __nv_bfloat16 l2 = __float2bfloat16(v.z - __bfloat162float(h2));
            __nv_bfloat16 l3 = __float2bfloat16(v.w - __bfloat162float(h3));
            *reinterpret_cast<uint2*>(&Ahi[r * KP + k]) = make_uint2(pack_bf2(h0, h1), pack_bf2(h2, h3));
            *reinterpret_cast<uint2*>(&Alo[r * KP + k]) = make_uint2(pack_bf2(l0, l1), pack_bf2(l2, l3));
        }
        for (int base = tid * 8; base < NOUT * 64; base += 256 * 8) {
            int nn = base >> 6, k = base & 63;
            *reinterpret_cast<uint4*>(&Bhi[nn * KP + k]) =
                *reinterpret_cast<const uint4*>(&Wh[nn * 128 + kk + k]);
            *reinterpret_cast<uint4*>(&Blo[nn * KP + k]) =
                *reinterpret_cast<const uint4*>(&Wl[nn * 128 + kk + k]);
        }
        __syncthreads();

#pragma unroll
        for (int kt = 0; kt < 4; kt++) {
            const int k0 = kt * 16;
            uint32_t ah[4], al[4];
            const int ra = (mrow + g) * KP + k0 + tq * 2;
            const int rb = (mrow + g + 8) * KP + k0 + tq * 2;
            ah[0] = *reinterpret_cast<const uint32_t*>(&Ahi[ra]);
            ah[1] = *reinterpret_cast<const uint32_t*>(&Ahi[rb]);
            ah[2] = *reinterpret_cast<const uint32_t*>(&Ahi[ra + 8]);
            ah[3] = *reinterpret_cast<const uint32_t*>(&Ahi[rb + 8]);
            al[0] = *reinterpret_cast<const uint32_t*>(&Alo[ra]);
            al[1] = *reinterpret_cast<const uint32_t*>(&Alo[rb]);
            al[2] = *reinterpret_cast<const uint32_t*>(&Alo[ra + 8]);
            al[3] = *reinterpret_cast<const uint32_t*>(&Alo[rb + 8]);
#pragma unroll
            for (int nt = 0; nt < NT; nt++) {
                uint32_t bh[2], bl[2];
                const int rn = (nt * 8 + g) * KP + k0 + tq * 2;
                bh[0] = *reinterpret_cast<const uint32_t*>(&Bhi[rn]);
                bh[1] = *reinterpret_cast<const uint32_t*>(&Bhi[rn + 8]);
                bl[0] = *reinterpret_cast<const uint32_t*>(&Blo[rn]);
                bl[1] = *reinterpret_cast<const uint32_t*>(&Blo[rn + 8]);
                mma16816(acc[nt], ah, bh);
                mma16816(acc[nt], ah, bl);
                mma16816(acc[nt], al, bh);
            }
        }
    }

    const int r0g = row0 + mrow + g;
    const int r1g = r0g + 8;
    const float d0 = (r0g < n) ? g_dinv[r0g] : 0.f;
    const float d1 = (r1g < n) ? g_dinv[r1g] : 0.f;
#pragma unroll
    for (int nt = 0; nt < NT; nt++) {
        if (r0g < n) {
            __half2 o = __floats2half2_rn(d0 * acc[nt][0], d0 * acc[nt][1]);
            *reinterpret_cast<__half2*>(&s_out[(size_t)r0g * NOUT + nt * 8 + tq * 2]) = o;
        }
        if (r1g < n) {
            __half2 o = __floats2half2_rn(d1 * acc[nt][2], d1 * acc[nt][3]);
            *reinterpret_cast<__half2*>(&s_out[(size_t)r1g * NOUT + nt * 8 + tq * 2]) = o;
        }
    }
}

// ---- CSR gather: one warp per destination row -------------------------------------
// fp16 messages, fp32 accumulation.
// LAYER==1: lane owns 4 feats; writes fp16 agg1.
// LAYER==2: lane owns 2 feats; fused epilogue -> d_out fp32.
template <int LAYER>
__global__ void k_gather(const float* __restrict__ b2, float* __restrict__ out, int n)
{
    const int lane = threadIdx.x & 31;
    const int wid  = (blockIdx.x * blockDim.x + threadIdx.x) >> 5;
    if (wid >= n) return;

    const int beg = g_rowptr[wid];
    const int end = g_rowptr[wid + 1];

    if (LAYER == 1) {
        const uint2* sp = reinterpret_cast<const uint2*>(g_s1);  // 4 halfs per elem
        uint2 sv = sp[(size_t)wid * 32 + lane];                  // self loop
        float2 p0 = __half22float2(*reinterpret_cast<__half2*>(&sv.x));
        float2 p1 = __half22float2(*reinterpret_cast<__half2*>(&sv.y));
        float4 a0 = make_float4(p0.x, p0.y, p1.x, p1.y);
        float4 a1 = make_float4(0.f, 0.f, 0.f, 0.f);
        float4 a2 = make_float4(0.f, 0.f, 0.f, 0.f);
        float4 a3 = make_float4(0.f, 0.f, 0.f, 0.f);
        int j = beg;
        for (; j + 4 <= end; j += 4) {
            int u0 = g_csr[j], u1 = g_csr[j + 1], u2 = g_csr[j + 2], u3 = g_csr[j + 3];
            uint2 v0 = sp[(size_t)u0 * 32 + lane];
            uint2 v1 = sp[(size_t)u1 * 32 + lane];
            uint2 v2 = sp[(size_t)u2 * 32 + lane];
            uint2 v3 = sp[(size_t)u3 * 32 + lane];
            float2 q0, q1;
            q0 = __half22float2(*reinterpret_cast<__half2*>(&v0.x));
            q1 = __half22float2(*reinterpret_cast<__half2*>(&v0.y));
            a0.x += q0.x; a0.y += q0.y; a0.z += q1.x; a0.w += q1.y;
            q0 = __half22float2(*reinterpret_cast<__half2*>(&v1.x));
            q1 = __half22float2(*reinterpret_cast<__half2*>(&v1.y));
            a1.x += q0.x; a1.y += q0.y; a1.z += q1.x; a1.w += q1.y;
            q0 = __half22float2(*reinterpret_cast<__half2*>(&v2.x));
            q1 = __half22float2(*reinterpret_cast<__half2*>(&v2.y));
            a2.x += q0.x; a2.y += q0.y; a2.z += q1.x; a2.w += q1.y;
            q0 = __half22float2(*reinterpret_cast<__half2*>(&v3.x));
            q1 = __half22float2(*reinterpret_cast<__half2*>(&v3.y));
            a3.x += q0.x; a3.y += q0.y; a3.z += q1.x; a3.w += q1.y;
        }
        for (; j < end; j++) {
            uint2 v = sp[(size_t)g_csr[j] * 32 + lane];
            float2 q0 = __half22float2(*reinterpret_cast<__half2*>(&v.x));
            float2 q1 = __half22float2(*reinterpret_cast<__half2*>(&v.y));
            a0.x += q0.x; a0.y += q0.y; a0.z += q1.x; a0.w += q1.y;
        }
        a0.x += a1.x + a2.x + a3.x;
        a0.y += a1.y + a2.y + a3.y;
        a0.z += a1.z + a2.z + a3.z;
        a0.w += a1.w + a2.w + a3.w;
        __half2 o0 = __floats2half2_rn(a0.x, a0.y);
        __half2 o1 = __floats2half2_rn(a0.z, a0.w);
        uint2 ov = make_uint2(*reinterpret_cast<uint32_t*>(&o0), *reinterpret_cast<uint32_t*>(&o1));
        reinterpret_cast<uint2*>(g_agg1h)[(size_t)wid * 32 + lane] = ov;
    } else {
        const uint32_t* sp = reinterpret_cast<const uint32_t*>(g_s2);  // half2 per elem
        uint32_t sv = sp[(size_t)wid * 32 + lane];
        float2 a0 = __half22float2(*reinterpret_cast<__half2*>(&sv));  // self loop
        float2 a1 = make_float2(0.f, 0.f);
        float2 a2 = make_float2(0.f, 0.f);
        float2 a3 = make_float2(0.f, 0.f);
        int j = beg;
        for (; j + 4 <= end; j += 4) {
            int u0 = g_csr[j], u1 = g_csr[j + 1], u2 = g_csr[j + 2], u3 = g_csr[j + 3];
            uint32_t v0 = sp[(size_t)u0 * 32 + lane];
            uint32_t v1 = sp[(size_t)u1 * 32 + lane];
            uint32_t v2 = sp[(size_t)u2 * 32 + lane];
            uint32_t v3 = sp[(size_t)u3 * 32 + lane];
            float2 q;
            q = __half22float2(*reinterpret_cast<__half2*>(&v0)); a0.x += q.x; a0.y += q.y;
            q = __half22float2(*reinterpret_cast<__half2*>(&v1)); a1.x += q.x; a1.y += q.y;
            q = __half22float2(*reinterpret_cast<__half2*>(&v2)); a2.x += q.x; a2.y += q.y;
            q = __half22float2(*reinterpret_cast<__half2*>(&v3)); a3.x += q.x; a3.y += q.y;
        }
        for (; j < end; j++) {
            uint32_t v = sp[(size_t)g_csr[j] * 32 + lane];
            float2 q = __half22float2(*reinterpret_cast<__half2*>(&v));
            a0.x += q.x; a0.y += q.y;
        }
        a0.x += a1.x + a2.x + a3.x;
        a0.y += a1.y + a2.y + a3.y;
        float di = g_dinv[wid];
        float2 r;
        r.x = di * a0.x + b2[lane * 2 + 0];
        r.y = di * a0.y + b2[lane * 2 + 1];
        reinterpret_cast<float2*>(out)[(size_t)wid * 32 + lane] = r;
    }
}

// -----------------------------------------------------------------------------
extern "C" void kernel_launch(void* const* d_in, const int* in_sizes, int n_in,
                              void* d_out, int out_size)
{
    const float* x  = (const float*)d_in[0];
    const int*   ew = (const int*)d_in[1];
    const float* W1 = (const float*)d_in[2];
    const float* b1 = (const float*)d_in[3];
    const float* W2 = (const float*)d_in[4];
    const float* b2 = (const float*)d_in[5];

    const int n = in_sizes[0] / HID;   // 100000
    const int E = in_sizes[1] / 2;     // 1600000
    const int nblk_scan = (n + SCAN_BLK - 1) / SCAN_BLK;   // 196 <= MAXSB

    const int smem1 = (2 * 128 * KP + 2 * HID * KP) * 2;   // 73728 B
    const int smem2 = (2 * 128 * KP + 2 * ODIM * KP) * 2;  // 55296 B
    cudaFuncSetAttribute(k_tgemm<HID, 1>, cudaFuncAttributeMaxDynamicSharedMemorySize, smem1);
    cudaFuncSetAttribute(k_tgemm<ODIM, 2>, cudaFuncAttributeMaxDynamicSharedMemorySize, smem2);

    // fused pre-pass (detect + zero cnt/flags + W conv)
    k_pre<<<(n + 255) / 256, 256>>>(ew, W1, W2, n);

    // CSR build + dinv (scan is single-kernel decoupled lookback)
    k_count<<<(E + 255) / 256, 256>>>(ew, E);
    k_scan<<<nblk_scan, SCAN_BLK>>>(n, E);
    k_fill<<<(E + 255) / 256, 256>>>(ew, E);

    const int gblk = (n + 127) / 128;
    // layer 1
    k_tgemm<HID, 1><<<gblk, 256, smem1>>>(x, nullptr, n);
    k_gather<1><<<(n + 7) / 8, 256>>>(nullptr, nullptr, n);

    // layer 2 (bias = b1 fused into A staging; epilogue fused into gather)
    k_tgemm<ODIM, 2><<<gblk, 256, smem2>>>(nullptr, b1, n);
    k_gather<2><<<(n + 7) / 8, 256>>>(b2, (float*)d_out, n);
}

// round 11
// speedup vs baseline: 1.1376x; 1.1376x over previous
#include <cuda_runtime.h>
#include <cuda_bf16.h>
#include <cuda_fp16.h>
#include <cstddef>
#include <cstdint>

// ---------------------------------------------------------------------------
// 2-layer GCN.
//   xw1 = X @ W1 (tensor cores);  agg1[d] = dinv[d]*xw1[d] + sum dinv[u]*xw1[u]
//   s2  = dinv * ((dinv*agg1 + b1) @ W2);  out[d] = dinv[d]*(s2[d]+sum s2[u]) + b2
// CSR build runs on a SIDE STREAM overlapped with GEMM1 (fork/join via events).
// GEMMs: mma.sync bf16 hi/lo split. Messages/agg fp16, accumulation fp32.
// ---------------------------------------------------------------------------

#define NMAX 100000
#define EMAX 1700000
#define HID 128
#define ODIM 64
#define SCAN_BLK 512
#define KP 72   // padded K-chunk stride (conflict-free frag LDS)

__device__ float  g_dinv[NMAX];
__device__ __align__(16) __half g_s1[(size_t)NMAX * HID];     // raw xw1, fp16
__device__ __align__(16) __half g_agg1h[(size_t)NMAX * HID];  // fp16 aggregate (dinv applied)
__device__ __align__(16) __half g_s2[(size_t)NMAX * ODIM];    // fp16 messages, layer 2
__device__ int    g_is64;

__device__ int g_cnt[NMAX];
__device__ int g_rowptr[NMAX + 1];
__device__ int g_cursor[NMAX];
__device__ int g_csr[EMAX];
__device__ int g_bsum[1024];

__device__ __align__(16) __nv_bfloat16 g_w1t_hi[HID * HID], g_w1t_lo[HID * HID];   // [n][k]
__device__ __align__(16) __nv_bfloat16 g_w2t_hi[ODIM * HID], g_w2t_lo[ODIM * HID]; // [n][k]

// ---- fused pre-pass: dtype detect + cnt zero + W conversion -----------------
__global__ void k_pre(const int* __restrict__ ew,
                      const float* __restrict__ W1, const float* __restrict__ W2, int n)
{
    int i = blockIdx.x * blockDim.x + threadIdx.x;

    if (blockIdx.x == 0) {
        __shared__ int any;
        if (threadIdx.x == 0) any = 0;
        __syncthreads();
        for (int j = threadIdx.x; j < 2048; j += blockDim.x)
            if (ew[2 * j + 1] != 0) any = 1;
        __syncthreads();
        if (threadIdx.x == 0) g_is64 = (any == 0) ? 1 : 0;
    }

    if (i < n) g_cnt[i] = 0;

    if (i < HID * HID) {
        int nn = i >> 7, k = i & 127;
        float v = W1[k * HID + nn];
        __nv_bfloat16 h = __float2bfloat16(v);
        g_w1t_hi[i] = h;
        g_w1t_lo[i] = __float2bfloat16(v - __bfloat162float(h));
    }
    if (i < ODIM * HID) {
        int nn = i >> 7, k = i & 127;
        float v = W2[k * ODIM + nn];
        __nv_bfloat16 h = __float2bfloat16(v);
        g_w2t_hi[i] = h;
        g_w2t_lo[i] = __float2bfloat16(v - __bfloat162float(h));
    }
}

__device__ __forceinline__ int edge_at(const int* __restrict__ w, int i, int is64) {
    return is64 ? w[2 * (size_t)i] : w[i];
}

// ---- CSR build (side stream) --------------------------------------------------
__global__ void k_count(const int* __restrict__ w, int E) {
    int is64 = g_is64;
    const int* dst = w + (size_t)E * (1 + is64);
    int i = blockIdx.x * blockDim.x + threadIdx.x;
    if (i < E) atomicAdd(&g_cnt[edge_at(dst, i, is64)], 1);
}

__global__ void k_scan1(int n) {
    __shared__ int sh[SCAN_BLK];
    int i = blockIdx.x * SCAN_BLK + threadIdx.x;
    int v = (i < n) ? g_cnt[i] : 0;
    sh[threadIdx.x] = v;
    __syncthreads();
    for (int off = 1; off < SCAN_BLK; off <<= 1) {
        int t = (threadIdx.x >= off) ? sh[threadIdx.x - off] : 0;
        __syncthreads();
        sh[threadIdx.x] += t;
        __syncthreads();
    }
    if (i < n) g_rowptr[i] = sh[threadIdx.x] - v;
    if (threadIdx.x == SCAN_BLK - 1) g_bsum[blockIdx.x] = sh[SCAN_BLK - 1];
}

__global__ void k_scan2(int nblk) {
    __shared__ int sh[1024];
    int v = (threadIdx.x < nblk) ? g_bsum[threadIdx.x] : 0;
    sh[threadIdx.x] = v;
    __syncthreads();
    for (int off = 1; off < 1024; off <<= 1) {
        int t = (threadIdx.x >= off) ? sh[threadIdx.x - off] : 0;
        __syncthreads();
        sh[threadIdx.x] += t;
        __syncthreads();
    }
    if (threadIdx.x < nblk) g_bsum[threadIdx.x] = sh[threadIdx.x] - v;
}

__global__ void k_scan3(int n, int E) {
    int i = blockIdx.x * blockDim.x + threadIdx.x;
    if (i < n) {
        int rp = g_rowptr[i] + g_bsum[i / SCAN_BLK];
        g_rowptr[i] = rp;
        g_cursor[i] = rp;
        g_dinv[i]   = rsqrtf((float)g_cnt[i] + 1.0f);
        if (i == n - 1) g_rowptr[n] = E;
    }
}

__global__ void k_fill(const int* __restrict__ w, int E) {
    int is64 = g_is64;
    const int* src = w;
    const int* dst = w + (size_t)E * (1 + is64);
    int i = blockIdx.x * blockDim.x + threadIdx.x;
    if (i < E) {
        int u = edge_at(src, i, is64);
        int v = edge_at(dst, i, is64);
        int pos = atomicAdd(&g_cursor[v], 1);
        g_csr[pos] = u;
    }
}

// ---- tensor-core GEMM -----------------------------------------------------------
__device__ __forceinline__ void mma16816(float c[4], const uint32_t a[4], const uint32_t b[2]) {
    asm volatile(
        "mma.sync.aligned.m16n8k16.row.col.f32.bf16.bf16.f32 "
        "{%0,%1,%2,%3}, {%4,%5,%6,%7}, {%8,%9}, {%0,%1,%2,%3};\n"
        : "+f"(c[0]), "+f"(c[1]), "+f"(c[2]), "+f"(c[3])
        : "r"(a[0]), "r"(a[1]), "r"(a[2]), "r"(a[3]), "r"(b[0]), "r"(b[1]));
}

__device__ __forceinline__ uint32_t pack_bf2(__nv_bfloat16 a, __nv_bfloat16 b) {
    return (uint32_t)__bfloat16_as_ushort(a) | ((uint32_t)__bfloat16_as_ushort(b) << 16);
}

// Block: 128 rows x NOUT cols, 256 threads. K in two 64-chunks.
// LAYER==1: A = x (fp32); epilogue writes RAW acc (dinv deferred to gather1).
// LAYER==2: A = g_agg1h (fp16), dinv*v + b1 fused on load; epilogue scales by dinv.
template <int NOUT, int LAYER>
__global__ void __launch_bounds__(256) k_tgemm(
    const float* __restrict__ A_in, const float* __restrict__ bias, int n)
{
    constexpr int NT = NOUT / 8;
    extern __shared__ __nv_bfloat16 sm[];
    __nv_bfloat16* Ahi = sm;                    // [128][KP]
    __nv_bfloat16* Alo = Ahi + 128 * KP;
    __nv_bfloat16* Bhi = Alo + 128 * KP;        // [NOUT][KP]
    __nv_bfloat16* Blo = Bhi + NOUT * KP;

    __half* s_out = (LAYER == 1) ? g_s1 : g_s2;
    const __nv_bfloat16* Wh = (LAYER == 1) ? g_w1t_hi : g_w2t_hi;
    const __nv_bfloat16* Wl = (LAYER == 1) ? g_w1t_lo : g_w2t_lo;

    const int tid  = threadIdx.x;
    const int row0 = blockIdx.x * 128;
    const int w = tid >> 5, lane = tid & 31;
    const int g = lane >> 2, tq = lane & 3;
    const int mrow = w * 16;

    float acc[NT][4];
#pragma unroll
    for (int nt = 0; nt < NT; nt++)
#pragma unroll
        for (int j = 0; j < 4; j++) acc[nt][j] = 0.0f;

#pragma unroll
    for (int kk = 0; kk < 128; kk += 64) {
        if (kk) __syncthreads();

        for (int base = tid * 4; base < 128 * 64; base += 256 * 4) {
            int r = base >> 6, k = base & 63;
            int row = row0 + r;
            float4 v = make_float4(0.f, 0.f, 0.f, 0.f);
            if (row < n) {
                if (LAYER == 1) {
                    v = *reinterpret_cast<const float4*>(&A_in[(size_t)row * 128 + kk + k]);
                } else {
                    uint2 hv = *reinterpret_cast<const uint2*>(&g_agg1h[(size_t)row * 128 + kk + k]);
                    float2 p0 = __half22float2(*reinterpret_cast<__half2*>(&hv.x));
                    float2 p1 = __half22float2(*reinterpret_cast<__half2*>(&hv.y));
                    float d = g_dinv[row];
                    float4 bb = *reinterpret_cast<const float4*>(&bias[kk + k]);
                    v.x = fmaf(d, p0.x, bb.x); v.y = fmaf(d, p0.y, bb.y);
                    v.z = fmaf(d, p1.x, bb.z); v.w = fmaf(d, p1.y, bb.w);
                }
            }
            __nv_bfloat16 h0 = __float2bfloat16(v.x), h1 = __float2bfloat16(v.y);
            __nv_bfloat16 h2 = __float2bfloat16(v.z), h3 = __float2bfloat16(v.w);
            __nv_bfloat16 l0 = __float2bfloat16(v.x - __bfloat162float(h0));
            __nv_bfloat16 l1 = __float2bfloat16(v.y - __bfloat162float(h1));
            __nv_bfloat16 l2 = __float2bfloat16(v.z - __bfloat162float(h2));
            __nv_bfloat16 l3 = __float2bfloat16(v.w - __bfloat162float(h3));
            *reinterpret_cast<uint2*>(&Ahi[r * KP + k]) = make_uint2(pack_bf2(h0, h1), pack_bf2(h2, h3));
            *reinterpret_cast<uint2*>(&Alo[r * KP + k]) = make_uint2(pack_bf2(l0, l1), pack_bf2(l2, l3));
        }
        for (int base = tid * 8; base < NOUT * 64; base += 256 * 8) {
            int nn = base >> 6, k = base & 63;
            *reinterpret_cast<uint4*>(&Bhi[nn * KP + k]) =
                *reinterpret_cast<const uint4*>(&Wh[nn * 128 + kk + k]);
            *reinterpret_cast<uint4*>(&Blo[nn * KP + k]) =
                *reinterpret_cast<const uint4*>(&Wl[nn * 128 + kk + k]);
        }
        __syncthreads();

#pragma unroll
        for (int kt = 0; kt < 4; kt++) {
            const int k0 = kt * 16;
            uint32_t ah[4], al[4];
            const int ra = (mrow + g) * KP + k0 + tq * 2;
            const int rb = (mrow + g + 8) * KP + k0 + tq * 2;
            ah[0] = *reinterpret_cast<const uint32_t*>(&Ahi[ra]);
            ah[1] = *reinterpret_cast<const uint32_t*>(&Ahi[rb]);
            ah[2] = *reinterpret_cast<const uint32_t*>(&Ahi[ra + 8]);
            ah[3] = *reinterpret_cast<const uint32_t*>(&Ahi[rb + 8]);
            al[0] = *reinterpret_cast<const uint32_t*>(&Alo[ra]);
            al[1] = *reinterpret_cast<const uint32_t*>(&Alo[rb]);
            al[2] = *reinterpret_cast<const uint32_t*>(&Alo[ra + 8]);
            al[3] = *reinterpret_cast<const uint32_t*>(&Alo[rb + 8]);
#pragma unroll
            for (int nt = 0; nt < NT; nt++) {
                uint32_t bh[2], bl[2];
                const int rn = (nt * 8 + g) * KP + k0 + tq * 2;
                bh[0] = *reinterpret_cast<const uint32_t*>(&Bhi[rn]);
                bh[1] = *reinterpret_cast<const uint32_t*>(&Bhi[rn + 8]);
                bl[0] = *reinterpret_cast<const uint32_t*>(&Blo[rn]);
                bl[1] = *reinterpret_cast<const uint32_t*>(&Blo[rn + 8]);
                mma16816(acc[nt], ah, bh);
                mma16816(acc[nt], ah, bl);
                mma16816(acc[nt], al, bh);
            }
        }
    }

    const int r0g = row0 + mrow + g;
    const int r1g = r0g + 8;
    float d0 = 1.0f, d1 = 1.0f;
    if (LAYER == 2) {
        d0 = (r0g < n) ? g_dinv[r0g] : 0.f;
        d1 = (r1g < n) ? g_dinv[r1g] : 0.f;
    }
#pragma unroll
    for (int nt = 0; nt < NT; nt++) {
        if (r0g < n) {
            __half2 o = __floats2half2_rn(d0 * acc[nt][0], d0 * acc[nt][1]);
            *reinterpret_cast<__half2*>(&s_out[(size_t)r0g * NOUT + nt * 8 + tq * 2]) = o;
        }
        if (r1g < n) {
            __half2 o = __floats2half2_rn(d1 * acc[nt][2], d1 * acc[nt][3]);
            *reinterpret_cast<__half2*>(&s_out[(size_t)r1g * NOUT + nt * 8 + tq * 2]) = o;
        }
    }
}

// ---- CSR gather ------------------------------------------------------------------
// LAYER==1: agg1h[d] = dinv[d]*s1[d] + sum dinv[u]*s1[u]   (dinv applied here)
// LAYER==2: out[d]   = dinv[d]*(s2[d] + sum s2[u]) + b2
template <int LAYER>
__global__ void k_gather(const float* __restrict__ b2, float* __restrict__ out, int n)
{
    const int lane = threadIdx.x & 31;
    const int wid  = (blockIdx.x * blockDim.x + threadIdx.x) >> 5;
    if (wid >= n) return;

    const int beg = g_rowptr[wid];
    const int end = g_rowptr[wid + 1];

    if (LAYER == 1) {
        const uint2* sp = reinterpret_cast<const uint2*>(g_s1);  // 4 halfs per elem
        const float ds = g_dinv[wid];
        uint2 sv = sp[(size_t)wid * 32 + lane];                  // self loop
        float2 p0 = __half22float2(*reinterpret_cast<__half2*>(&sv.x));
        float2 p1 = __half22float2(*reinterpret_cast<__half2*>(&sv.y));
        float4 a0 = make_float4(ds * p0.x, ds * p0.y, ds * p1.x, ds * p1.y);
        float4 a1 = make_float4(0.f, 0.f, 0.f, 0.f);
        float4 a2 = make_float4(0.f, 0.f, 0.f, 0.f);
        float4 a3 = make_float4(0.f, 0.f, 0.f, 0.f);
        int j = beg;
        for (; j + 4 <= end; j += 4) {
            int u0 = g_csr[j], u1 = g_csr[j + 1], u2 = g_csr[j + 2], u3 = g_csr[j + 3];
            float d0 = g_dinv[u0], d1 = g_dinv[u1], d2 = g_dinv[u2], d3 = g_dinv[u3];
            uint2 v0 = sp[(size_t)u0 * 32 + lane];
            uint2 v1 = sp[(size_t)u1 * 32 + lane];
            uint2 v2 = sp[(size_t)u2 * 32 + lane];
            uint2 v3 = sp[(size_t)u3 * 32 + lane];
            float2 q0, q1;
            q0 = __half22float2(*reinterpret_cast<__half2*>(&v0.x));
            q1 = __half22float2(*reinterpret_cast<__half2*>(&v0.y));
            a0.x = fmaf(d0, q0.x, a0.x); a0.y = fmaf(d0, q0.y, a0.y);
            a0.z = fmaf(d0, q1.x, a0.z); a0.w = fmaf(d0, q1.y, a0.w);
            q0 = __half22float2(*reinterpret_cast<__half2*>(&v1.x));
            q1 = __half22float2(*reinterpret_cast<__half2*>(&v1.y));
            a1.x = fmaf(d1, q0.x, a1.x); a1.y = fmaf(d1, q0.y, a1.y);
            a1.z = fmaf(d1, q1.x, a1.z); a1.w = fmaf(d1, q1.y, a1.w);
            q0 = __half22float2(*reinterpret_cast<__half2*>(&v2.x));
            q1 = __half22float2(*reinterpret_cast<__half2*>(&v2.y));
            a2.x = fmaf(d2, q0.x, a2.x); a2.y = fmaf(d2, q0.y, a2.y);
            a2.z = fmaf(d2, q1.x, a2.z); a2.w = fmaf(d2, q1.y, a2.w);
            q0 = __half22float2(*reinterpret_cast<__half2*>(&v3.x));
            q1 = __half22float2(*reinterpret_cast<__half2*>(&v3.y));
            a3.x = fmaf(d3, q0.x, a3.x); a3.y = fmaf(d3, q0.y, a3.y);
            a3.z = fmaf(d3, q1.x, a3.z); a3.w = fmaf(d3, q1.y, a3.w);
        }
        for (; j < end; j++) {
            int u = g_csr[j];
            float d = g_dinv[u];
            uint2 v = sp[(size_t)u * 32 + lane];
            float2 q0 = __half22float2(*reinterpret_cast<__half2*>(&v.x));
            float2 q1 = __half22float2(*reinterpret_cast<__half2*>(&v.y));
            a0.x = fmaf(d, q0.x, a0.x); a0.y = fmaf(d, q0.y, a0.y);
            a0.z = fmaf(d, q1.x, a0.z); a0.w = fmaf(d, q1.y, a0.w);
        }
        a0.x += a1.x + a2.x + a3.x;
        a0.y += a1.y + a2.y + a3.y;
        a0.z += a1.z + a2.z + a3.z;
        a0.w += a1.w + a2.w + a3.w;
        __half2 o0 = __floats2half2_rn(a0.x, a0.y);
        __half2 o1 = __floats2half2_rn(a0.z, a0.w);
        uint2 ov = make_uint2(*reinterpret_cast<uint32_t*>(&o0), *reinterpret_cast<uint32_t*>(&o1));
        reinterpret_cast<uint2*>(g_agg1h)[(size_t)wid * 32 + lane] = ov;
    } else {
        const uint32_t* sp = reinterpret_cast<const uint32_t*>(g_s2);  // half2 per elem
        uint32_t sv = sp[(size_t)wid * 32 + lane];
        float2 a0 = __half22float2(*reinterpret_cast<__half2*>(&sv));  // self loop
        float2 a1 = make_float2(0.f, 0.f);
        float2 a2 = make_float2(0.f, 0.f);
        float2 a3 = make_float2(0.f, 0.f);
        int j = beg;
        for (; j + 4 <= end; j += 4) {
            int u0 = g_csr[j], u1 = g_csr[j + 1], u2 = g_csr[j + 2], u3 = g_csr[j + 3];
            uint32_t v0 = sp[(size_t)u0 * 32 + lane];
            uint32_t v1 = sp[(size_t)u1 * 32 + lane];
            uint32_t v2 = sp[(size_t)u2 * 32 + lane];
            uint32_t v3 = sp[(size_t)u3 * 32 + lane];
            float2 q;
            q = __half22float2(*reinterpret_cast<__half2*>(&v0)); a0.x += q.x; a0.y += q.y;
            q = __half22float2(*reinterpret_cast<__half2*>(&v1)); a1.x += q.x; a1.y += q.y;
            q = __half22float2(*reinterpret_cast<__half2*>(&v2)); a2.x += q.x; a2.y += q.y;
            q = __half22float2(*reinterpret_cast<__half2*>(&v3)); a3.x += q.x; a3.y += q.y;
        }
        for (; j < end; j++) {
            uint32_t v = sp[(size_t)g_csr[j] * 32 + lane];
            float2 q = __half22float2(*reinterpret_cast<__half2*>(&v));
            a0.x += q.x; a0.y += q.y;
        }
        a0.x += a1.x + a2.x + a3.x;
        a0.y += a1.y + a2.y + a3.y;
        float di = g_dinv[wid];
        float2 r;
        r.x = di * a0.x + b2[lane * 2 + 0];
        r.y = di * a0.y + b2[lane * 2 + 1];
        reinterpret_cast<float2*>(out)[(size_t)wid * 32 + lane] = r;
    }
}

// -----------------------------------------------------------------------------
static cudaStream_t g_side = nullptr;
static cudaEvent_t  g_evFork = nullptr, g_evJoin = nullptr;

extern "C" void kernel_launch(void* const* d_in, const int* in_sizes, int n_in,
                              void* d_out, int out_size)
{
    const float* x  = (const float*)d_in[0];
    const int*   ew = (const int*)d_in[1];
    const float* W1 = (const float*)d_in[2];
    const float* b1 = (const float*)d_in[3];
    const float* W2 = (const float*)d_in[4];
    const float* b2 = (const float*)d_in[5];

    const int n = in_sizes[0] / HID;   // 100000
    const int E = in_sizes[1] / 2;     // 1600000
    const int nblk_scan = (n + SCAN_BLK - 1) / SCAN_BLK;

    if (!g_side) {
        cudaStreamCreateWithFlags(&g_side, cudaStreamNonBlocking);
        cudaEventCreateWithFlags(&g_evFork, cudaEventDisableTiming);
        cudaEventCreateWithFlags(&g_evJoin, cudaEventDisableTiming);
    }

    const int smem1 = (2 * 128 * KP + 2 * HID * KP) * 2;   // 73728 B
    const int smem2 = (2 * 128 * KP + 2 * ODIM * KP) * 2;  // 55296 B
    cudaFuncSetAttribute(k_tgemm<HID, 1>, cudaFuncAttributeMaxDynamicSharedMemorySize, smem1);
    cudaFuncSetAttribute(k_tgemm<ODIM, 2>, cudaFuncAttributeMaxDynamicSharedMemorySize, smem2);

    // pre: detect + zero + W conv (main stream)
    k_pre<<<(n + 255) / 256, 256>>>(ew, W1, W2, n);

    // fork: CSR build chain on side stream, concurrent with GEMM1
    cudaEventRecord(g_evFork, 0);
    cudaStreamWaitEvent(g_side, g_evFork, 0);
    k_count<<<(E + 255) / 256, 256, 0, g_side>>>(ew, E);
    k_scan1<<<nblk_scan, SCAN_BLK, 0, g_side>>>(n);
    k_scan2<<<1, 1024, 0, g_side>>>(nblk_scan);
    k_scan3<<<(n + 255) / 256, 256, 0, g_side>>>(n, E);
    k_fill<<<(E + 255) / 256, 256, 0, g_side>>>(ew, E);
    cudaEventRecord(g_evJoin, g_side);

    const int gblk = (n + 127) / 128;
    // GEMM1 on main stream (independent of CSR/dinv; dinv deferred to gather1)
    k_tgemm<HID, 1><<<gblk, 256, smem1>>>(x, nullptr, n);

    // join: gather1 needs CSR + dinv + s1
    cudaStreamWaitEvent(0, g_evJoin, 0);
    k_gather<1><<<(n + 7) / 8, 256>>>(nullptr, nullptr, n);

    // layer 2
    k_tgemm<ODIM, 2><<<gblk, 256, smem2>>>(nullptr, b1, n);
    k_gather<2><<<(n + 7) / 8, 256>>>(b2, (float*)d_out, n);
}